// round 3
// baseline (speedup 1.0000x reference)
#include <cuda_runtime.h>
#include <math.h>

#define N_NODES 50000
#define N_EDGES 800000
#define N_RELS  16
#define D       128

// ---------------- device scratch (static, no allocation) ----------------
__device__ float g_Y[(size_t)N_RELS * N_NODES * D];   // 409.6 MB transformed features
__device__ float g_G[(size_t)N_RELS * N_NODES];       // gate logits
__device__ float g_H1[(size_t)N_NODES * D];           // layer-0 output

// ---------------- helpers ----------------
__device__ __forceinline__ float to_tf32(float x) {
    unsigned u;
    asm("cvt.rna.tf32.f32 %0, %1;" : "=r"(u) : "f"(x));
    return __uint_as_float(u);
}

// ---------------- tf32 GEMM: C[r] = A(MxD) @ B[r](DxD) (+bias) ----------------
// block: 256 threads, tile 128x128, full K=128 in smem.
// As stride 132 floats (bank-conflict-free for A frags), Bs stride 136 (for B frags).
#define BM 128
#define AS_STRIDE 132
#define BS_STRIDE 136
#define GEMM_SMEM_BYTES ((BM*AS_STRIDE + D*BS_STRIDE) * 4)

extern __shared__ float smem_dyn[];

__global__ void __launch_bounds__(256, 1)
gemm_tf32_kernel(const float* __restrict__ A,     // M x D
                 const float* __restrict__ Ball,  // (R x) D x D
                 float* __restrict__ C,           // (R x) M x D
                 const float* __restrict__ bias,  // D or nullptr
                 int M)
{
    float* As = smem_dyn;                  // BM x AS_STRIDE
    float* Bs = smem_dyn + BM * AS_STRIDE; // D x BS_STRIDE

    const int r = blockIdx.y;
    const float* B = Ball + (size_t)r * D * D;
    float* Cr = C + (size_t)r * M * D;
    const int row0 = blockIdx.x * BM;
    const int tid = threadIdx.x;

    // Load A tile (convert to tf32). 128x128 floats = 4096 float4, 256 thr -> 16 each.
    for (int i = tid; i < BM * (D / 4); i += 256) {
        int rr = i >> 5;          // 32 float4 per row
        int c4 = (i & 31) << 2;
        float4 v = make_float4(0.f, 0.f, 0.f, 0.f);
        int gr = row0 + rr;
        if (gr < M) v = *(const float4*)(A + (size_t)gr * D + c4);
        v.x = to_tf32(v.x); v.y = to_tf32(v.y); v.z = to_tf32(v.z); v.w = to_tf32(v.w);
        *(float4*)(As + rr * AS_STRIDE + c4) = v;
    }
    // Load B tile (convert to tf32)
    for (int i = tid; i < D * (D / 4); i += 256) {
        int rr = i >> 5;
        int c4 = (i & 31) << 2;
        float4 v = *(const float4*)(B + rr * D + c4);
        v.x = to_tf32(v.x); v.y = to_tf32(v.y); v.z = to_tf32(v.z); v.w = to_tf32(v.w);
        *(float4*)(Bs + rr * BS_STRIDE + c4) = v;
    }
    __syncthreads();

    const int w = tid >> 5;
    const int lane = tid & 31;
    const int g = lane >> 2;      // groupID
    const int t = lane & 3;       // threadID_in_group
    const int wm = w & 3;         // 4 warps along M (32 rows each)
    const int wn = w >> 2;        // 2 warps along N (64 cols each)

    float acc[2][8][4];
    #pragma unroll
    for (int im = 0; im < 2; im++)
        #pragma unroll
        for (int jn = 0; jn < 8; jn++)
            #pragma unroll
            for (int k = 0; k < 4; k++) acc[im][jn][k] = 0.f;

    #pragma unroll
    for (int ks = 0; ks < 16; ks++) {
        const int kb = ks * 8;
        unsigned a[2][4];
        #pragma unroll
        for (int im = 0; im < 2; im++) {
            int rb = wm * 32 + im * 16 + g;
            a[im][0] = __float_as_uint(As[rb * AS_STRIDE + kb + t]);
            a[im][1] = __float_as_uint(As[(rb + 8) * AS_STRIDE + kb + t]);
            a[im][2] = __float_as_uint(As[rb * AS_STRIDE + kb + t + 4]);
            a[im][3] = __float_as_uint(As[(rb + 8) * AS_STRIDE + kb + t + 4]);
        }
        unsigned bf[8][2];
        #pragma unroll
        for (int jn = 0; jn < 8; jn++) {
            int col = wn * 64 + jn * 8 + g;
            bf[jn][0] = __float_as_uint(Bs[(kb + t) * BS_STRIDE + col]);
            bf[jn][1] = __float_as_uint(Bs[(kb + t + 4) * BS_STRIDE + col]);
        }
        #pragma unroll
        for (int im = 0; im < 2; im++)
            #pragma unroll
            for (int jn = 0; jn < 8; jn++) {
                asm volatile(
                    "mma.sync.aligned.m16n8k8.row.col.f32.tf32.tf32.f32 "
                    "{%0,%1,%2,%3}, {%4,%5,%6,%7}, {%8,%9}, {%0,%1,%2,%3};"
                    : "+f"(acc[im][jn][0]), "+f"(acc[im][jn][1]),
                      "+f"(acc[im][jn][2]), "+f"(acc[im][jn][3])
                    : "r"(a[im][0]), "r"(a[im][1]), "r"(a[im][2]), "r"(a[im][3]),
                      "r"(bf[jn][0]), "r"(bf[jn][1]));
            }
    }

    // Epilogue: C layout (16x8 tile): c0=(g,2t) c1=(g,2t+1) c2=(g+8,2t) c3=(g+8,2t+1)
    #pragma unroll
    for (int im = 0; im < 2; im++) {
        int rb = row0 + wm * 32 + im * 16 + g;
        #pragma unroll
        for (int jn = 0; jn < 8; jn++) {
            int col = wn * 64 + jn * 8 + 2 * t;
            float bx = 0.f, by = 0.f;
            if (bias) { bx = bias[col]; by = bias[col + 1]; }
            if (rb < M) {
                float2 v = make_float2(acc[im][jn][0] + bx, acc[im][jn][1] + by);
                *(float2*)(Cr + (size_t)rb * D + col) = v;
            }
            if (rb + 8 < M) {
                float2 v = make_float2(acc[im][jn][2] + bx, acc[im][jn][3] + by);
                *(float2*)(Cr + (size_t)(rb + 8) * D + col) = v;
            }
        }
    }
}

// ---------------- gate logits: G[r,n] = h[n,:] . gate_w[r,:] ----------------
__global__ void __launch_bounds__(256)
gate_kernel(const float* __restrict__ H,
            const float* __restrict__ GW)
{
    int node = (blockIdx.x * blockDim.x + threadIdx.x) >> 5;
    int lane = threadIdx.x & 31;
    if (node >= N_NODES) return;
    float4 hv = *(const float4*)(H + (size_t)node * D + lane * 4);
    #pragma unroll
    for (int r = 0; r < N_RELS; r++) {
        float4 wv = *(const float4*)(GW + r * D + lane * 4);
        float p = hv.x * wv.x + hv.y * wv.y + hv.z * wv.z + hv.w * wv.w;
        #pragma unroll
        for (int off = 16; off > 0; off >>= 1)
            p += __shfl_xor_sync(0xFFFFFFFFu, p, off);
        if (lane == 0) g_G[(size_t)r * N_NODES + node] = p;
    }
}

// ---------------- edge scatter: out[dst] += coef * Y[rel,src,:] ----------------
__global__ void __launch_bounds__(256)
scatter_kernel(const float* __restrict__ norm,
               const int* __restrict__ src,
               const int* __restrict__ dst,
               const int* __restrict__ rel,
               float* __restrict__ out)
{
    int e = (blockIdx.x * blockDim.x + threadIdx.x) >> 5;
    int lane = threadIdx.x & 31;
    if (e >= N_EDGES) return;
    int s = __ldg(src + e), d = __ldg(dst + e), r = __ldg(rel + e);
    float gl = g_G[(size_t)r * N_NODES + s];
    float coef = __ldg(norm + e) / (1.f + __expf(-gl));
    float4 v = *(const float4*)(&g_Y[((size_t)r * N_NODES + s) * D + lane * 4]);
    float* p = out + (size_t)d * D + lane * 4;
    asm volatile("red.global.add.v4.f32 [%0], {%1,%2,%3,%4};"
                 :: "l"(p), "f"(v.x * coef), "f"(v.y * coef),
                    "f"(v.z * coef), "f"(v.w * coef)
                 : "memory");
}

// ---------------- relu ----------------
__global__ void __launch_bounds__(256)
relu_kernel(float* __restrict__ x, int n)
{
    int i = blockIdx.x * blockDim.x + threadIdx.x;
    if (i < n) x[i] = fmaxf(x[i], 0.f);
}

// ---------------- launch ----------------
extern "C" void kernel_launch(void* const* d_in, const int* in_sizes, int n_in,
                              void* d_out, int out_size)
{
    const float* h   = (const float*)d_in[0];
    const float* nrm = (const float*)d_in[1];
    const float* W0  = (const float*)d_in[2];
    const float* b0  = (const float*)d_in[3];
    const float* lw0 = (const float*)d_in[4];
    const float* gw0 = (const float*)d_in[5];
    const float* W1  = (const float*)d_in[6];
    const float* b1  = (const float*)d_in[7];
    const float* lw1 = (const float*)d_in[8];
    const float* gw1 = (const float*)d_in[9];
    const int*   src = (const int*)d_in[10];
    const int*   dst = (const int*)d_in[11];
    const int*   rel = (const int*)d_in[12];
    float* out = (float*)d_out;

    cudaFuncSetAttribute(gemm_tf32_kernel,
                         cudaFuncAttributeMaxDynamicSharedMemorySize,
                         GEMM_SMEM_BYTES);

    float *Yp, *H1p;
    cudaGetSymbolAddress((void**)&Yp, g_Y);
    cudaGetSymbolAddress((void**)&H1p, g_H1);

    const int mblocks = (N_NODES + BM - 1) / BM;  // 391
    dim3 gridY(mblocks, N_RELS);
    dim3 gridL(mblocks, 1);
    const int gate_blocks = (N_NODES * 32 + 255) / 256;     // 6250
    const int scat_blocks = (N_EDGES * 32 + 255) / 256;     // 100000
    const int relu_blocks = (N_NODES * D + 255) / 256;

    // ---- layer 0 ----
    gate_kernel<<<gate_blocks, 256>>>(h, gw0);
    gemm_tf32_kernel<<<gridY, 256, GEMM_SMEM_BYTES>>>(h, W0, Yp, nullptr, N_NODES);
    gemm_tf32_kernel<<<gridL, 256, GEMM_SMEM_BYTES>>>(h, lw0, H1p, b0, N_NODES);
    scatter_kernel<<<scat_blocks, 256>>>(nrm, src, dst, rel, H1p);
    relu_kernel<<<relu_blocks, 256>>>(H1p, N_NODES * D);

    // ---- layer 1 ----
    gate_kernel<<<gate_blocks, 256>>>(H1p, gw1);
    gemm_tf32_kernel<<<gridY, 256, GEMM_SMEM_BYTES>>>(H1p, W1, Yp, nullptr, N_NODES);
    gemm_tf32_kernel<<<gridL, 256, GEMM_SMEM_BYTES>>>(H1p, lw1, out, b1, N_NODES);
    scatter_kernel<<<scat_blocks, 256>>>(nrm, src, dst, rel, out);
    (void)in_sizes; (void)n_in; (void)out_size;
}

// round 5
// speedup vs baseline: 1.4240x; 1.4240x over previous
#include <cuda_runtime.h>
#include <cstdint>
#include <math.h>

#define N_NODES 50000
#define N_EDGES 800000
#define N_RELS  16
#define D       128
#define RGROUP  2
#define NSTAGES (N_RELS / RGROUP)

// ---------------- device scratch (static, no allocation) ----------------
__device__ float g_Yr[(size_t)RGROUP * N_NODES * D];  // 51.2 MB reused Y slab (L2-resident)
__device__ float g_G[(size_t)N_RELS * N_NODES];       // gate logits
__device__ float g_H1[(size_t)N_NODES * D];           // layer-0 output
__device__ int   g_src_s[N_EDGES];                    // rel-sorted edge arrays
__device__ int   g_dst_s[N_EDGES];
__device__ float g_norm_s[N_EDGES];
__device__ int   g_cnt[N_RELS];
__device__ int   g_off[N_RELS + 1];
__device__ int   g_cur[N_RELS];

// ---------------- helpers ----------------
__device__ __forceinline__ float to_tf32(float x) {
    unsigned u;
    asm("cvt.rna.tf32.f32 %0, %1;" : "=r"(u) : "f"(x));
    return __uint_as_float(u);
}

// ---------------- edge bucketing (per call, deterministic) ----------------
__global__ void __launch_bounds__(32)
zero_cnt_kernel() {
    if (threadIdx.x < N_RELS) g_cnt[threadIdx.x] = 0;
}

__global__ void __launch_bounds__(256)
hist_kernel(const int* __restrict__ rel) {
    __shared__ int scnt[N_RELS];
    if (threadIdx.x < N_RELS) scnt[threadIdx.x] = 0;
    __syncthreads();
    int e = blockIdx.x * 256 + threadIdx.x;
    if (e < N_EDGES) atomicAdd(&scnt[rel[e]], 1);
    __syncthreads();
    if (threadIdx.x < N_RELS && scnt[threadIdx.x] > 0)
        atomicAdd(&g_cnt[threadIdx.x], scnt[threadIdx.x]);
}

__global__ void __launch_bounds__(32)
prefix_kernel() {
    if (threadIdx.x == 0) {
        int acc = 0;
        #pragma unroll
        for (int r = 0; r < N_RELS; r++) {
            g_off[r] = acc; g_cur[r] = acc; acc += g_cnt[r];
        }
        g_off[N_RELS] = acc;
    }
}

__global__ void __launch_bounds__(256)
reorder_kernel(const int* __restrict__ src, const int* __restrict__ dst,
               const float* __restrict__ nrm, const int* __restrict__ rel) {
    __shared__ int scnt[N_RELS];
    __shared__ int sbase[N_RELS];
    if (threadIdx.x < N_RELS) scnt[threadIdx.x] = 0;
    __syncthreads();
    int e = blockIdx.x * 256 + threadIdx.x;
    int r = 0, rank = 0;
    bool ok = (e < N_EDGES);
    if (ok) { r = rel[e]; rank = atomicAdd(&scnt[r], 1); }
    __syncthreads();
    if (threadIdx.x < N_RELS && scnt[threadIdx.x] > 0)
        sbase[threadIdx.x] = atomicAdd(&g_cur[threadIdx.x], scnt[threadIdx.x]);
    __syncthreads();
    if (ok) {
        int pos = sbase[r] + rank;
        g_src_s[pos] = src[e];
        g_dst_s[pos] = dst[e];
        g_norm_s[pos] = nrm[e];
    }
}

// ---------------- tf32 mma.sync GEMM ----------------
// C[ry] = A(BM rows x 128) @ B[ry]  (B row-major [K=128][N=128])
// 128 threads = 4 warps; warp w: 64 rows x cols [w*32, w*32+32)
#define BM 64
#define AS_STRIDE 132
#define BS_STRIDE 136
#define GEMM_SMEM ((BM * AS_STRIDE + D * BS_STRIDE) * 4)

extern __shared__ float smem_dyn[];

__global__ void __launch_bounds__(128, 2)
gemm_tf32_kernel(const float* __restrict__ A,     // M x D
                 const float* __restrict__ Ball,  // (gridDim.y x) D x D row-major
                 float* __restrict__ C,           // (gridDim.y x) M x D
                 const float* __restrict__ bias,  // D or nullptr
                 int M, size_t c_rel_stride)
{
    float* As = smem_dyn;                  // BM x AS_STRIDE
    float* Bs = smem_dyn + BM * AS_STRIDE; // D x BS_STRIDE

    const int ry = blockIdx.y;
    const float* B = Ball + (size_t)ry * D * D;
    float* Cr = C + (size_t)ry * c_rel_stride;
    const int row0 = blockIdx.x * BM;
    const int tid = threadIdx.x;

    // A tile: 64x128 floats = 2048 float4 / 128 thr = 16 iters
    for (int i = tid; i < BM * (D / 4); i += 128) {
        int rr = i >> 5;
        int c4 = (i & 31) << 2;
        float4 v = make_float4(0.f, 0.f, 0.f, 0.f);
        int gr = row0 + rr;
        if (gr < M) v = *(const float4*)(A + (size_t)gr * D + c4);
        v.x = to_tf32(v.x); v.y = to_tf32(v.y); v.z = to_tf32(v.z); v.w = to_tf32(v.w);
        *(float4*)(As + rr * AS_STRIDE + c4) = v;
    }
    // B tile: 128x128 floats = 4096 float4 / 128 thr = 32 iters
    for (int i = tid; i < D * (D / 4); i += 128) {
        int rr = i >> 5;
        int c4 = (i & 31) << 2;
        float4 v = *(const float4*)(B + rr * D + c4);
        v.x = to_tf32(v.x); v.y = to_tf32(v.y); v.z = to_tf32(v.z); v.w = to_tf32(v.w);
        *(float4*)(Bs + rr * BS_STRIDE + c4) = v;
    }
    __syncthreads();

    const int w = tid >> 5;       // warp: cols [w*32, w*32+32)
    const int lane = tid & 31;
    const int g = lane >> 2;
    const int t = lane & 3;

    float acc[4][4][4];
    #pragma unroll
    for (int im = 0; im < 4; im++)
        #pragma unroll
        for (int jn = 0; jn < 4; jn++)
            #pragma unroll
            for (int k = 0; k < 4; k++) acc[im][jn][k] = 0.f;

    #pragma unroll
    for (int ks = 0; ks < 16; ks++) {
        const int kb = ks * 8;
        unsigned a[4][4];
        #pragma unroll
        for (int im = 0; im < 4; im++) {
            int rb = im * 16 + g;
            a[im][0] = __float_as_uint(As[rb * AS_STRIDE + kb + t]);
            a[im][1] = __float_as_uint(As[(rb + 8) * AS_STRIDE + kb + t]);
            a[im][2] = __float_as_uint(As[rb * AS_STRIDE + kb + t + 4]);
            a[im][3] = __float_as_uint(As[(rb + 8) * AS_STRIDE + kb + t + 4]);
        }
        unsigned bf[4][2];
        #pragma unroll
        for (int jn = 0; jn < 4; jn++) {
            int col = w * 32 + jn * 8 + g;
            bf[jn][0] = __float_as_uint(Bs[(kb + t) * BS_STRIDE + col]);
            bf[jn][1] = __float_as_uint(Bs[(kb + t + 4) * BS_STRIDE + col]);
        }
        #pragma unroll
        for (int im = 0; im < 4; im++)
            #pragma unroll
            for (int jn = 0; jn < 4; jn++) {
                asm volatile(
                    "mma.sync.aligned.m16n8k8.row.col.f32.tf32.tf32.f32 "
                    "{%0,%1,%2,%3}, {%4,%5,%6,%7}, {%8,%9}, {%0,%1,%2,%3};"
                    : "+f"(acc[im][jn][0]), "+f"(acc[im][jn][1]),
                      "+f"(acc[im][jn][2]), "+f"(acc[im][jn][3])
                    : "r"(a[im][0]), "r"(a[im][1]), "r"(a[im][2]), "r"(a[im][3]),
                      "r"(bf[jn][0]), "r"(bf[jn][1]));
            }
    }

    #pragma unroll
    for (int im = 0; im < 4; im++) {
        int rb = row0 + im * 16 + g;
        #pragma unroll
        for (int jn = 0; jn < 4; jn++) {
            int col = w * 32 + jn * 8 + 2 * t;
            float bx = 0.f, by = 0.f;
            if (bias) { bx = __ldg(bias + col); by = __ldg(bias + col + 1); }
            if (rb < M) {
                float2 v = make_float2(acc[im][jn][0] + bx, acc[im][jn][1] + by);
                *(float2*)(Cr + (size_t)rb * D + col) = v;
            }
            if (rb + 8 < M) {
                float2 v = make_float2(acc[im][jn][2] + bx, acc[im][jn][3] + by);
                *(float2*)(Cr + (size_t)(rb + 8) * D + col) = v;
            }
        }
    }
}

// ---------------- gate logits: G[r,n] = h[n,:] . gate_w[r,:] ----------------
__global__ void __launch_bounds__(256)
gate_kernel(const float* __restrict__ H, const float* __restrict__ GW)
{
    int node = (blockIdx.x * blockDim.x + threadIdx.x) >> 5;
    int lane = threadIdx.x & 31;
    if (node >= N_NODES) return;
    float4 hv = *(const float4*)(H + (size_t)node * D + lane * 4);
    #pragma unroll
    for (int r = 0; r < N_RELS; r++) {
        float4 wv = *(const float4*)(GW + r * D + lane * 4);
        float p = hv.x * wv.x + hv.y * wv.y + hv.z * wv.z + hv.w * wv.w;
        #pragma unroll
        for (int off = 16; off > 0; off >>= 1)
            p += __shfl_xor_sync(0xFFFFFFFFu, p, off);
        if (lane == 0) g_G[(size_t)r * N_NODES + node] = p;
    }
}

// ---------------- stage scatter: edges of rels [r0, r0+RGROUP) ----------------
__global__ void __launch_bounds__(256)
scatter_stage_kernel(float* __restrict__ out, int r0)
{
    const int gw = (blockIdx.x * blockDim.x + threadIdx.x) >> 5;
    const int lane = threadIdx.x & 31;
    const int nwarp = (gridDim.x * blockDim.x) >> 5;
    const int e0 = g_off[r0];
    const int mid = g_off[r0 + 1];
    const int e1 = g_off[r0 + RGROUP];
    for (int p = e0 + gw; p < e1; p += nwarp) {
        int s = __ldg(g_src_s + p);
        int d = __ldg(g_dst_s + p);
        int r = (p < mid) ? r0 : (r0 + 1);
        float gl = g_G[(size_t)r * N_NODES + s];
        float coef = __ldg(g_norm_s + p) / (1.f + __expf(-gl));
        int local = r - r0;
        float4 v = *(const float4*)(&g_Yr[((size_t)local * N_NODES + s) * D + lane * 4]);
        float* ptr = out + (size_t)d * D + lane * 4;
        asm volatile("red.global.add.v4.f32 [%0], {%1,%2,%3,%4};"
                     :: "l"(ptr), "f"(v.x * coef), "f"(v.y * coef),
                        "f"(v.z * coef), "f"(v.w * coef)
                     : "memory");
    }
}

// ---------------- relu ----------------
__global__ void __launch_bounds__(256)
relu_kernel(float* __restrict__ x, int n)
{
    int i = blockIdx.x * blockDim.x + threadIdx.x;
    if (i < n) x[i] = fmaxf(x[i], 0.f);
}

// ---------------- launch ----------------
extern "C" void kernel_launch(void* const* d_in, const int* in_sizes, int n_in,
                              void* d_out, int out_size)
{
    const float* h   = (const float*)d_in[0];
    const float* nrm = (const float*)d_in[1];
    const float* W0  = (const float*)d_in[2];
    const float* b0  = (const float*)d_in[3];
    const float* lw0 = (const float*)d_in[4];
    const float* gw0 = (const float*)d_in[5];
    const float* W1  = (const float*)d_in[6];
    const float* b1  = (const float*)d_in[7];
    const float* lw1 = (const float*)d_in[8];
    const float* gw1 = (const float*)d_in[9];
    const int*   src = (const int*)d_in[10];
    const int*   dst = (const int*)d_in[11];
    const int*   rel = (const int*)d_in[12];
    float* out = (float*)d_out;

    cudaFuncSetAttribute(gemm_tf32_kernel,
                         cudaFuncAttributeMaxDynamicSharedMemorySize, GEMM_SMEM);

    float *Yp, *H1p;
    cudaGetSymbolAddress((void**)&Yp, g_Yr);
    cudaGetSymbolAddress((void**)&H1p, g_H1);

    const int mblocks = (N_NODES + BM - 1) / BM;            // 782
    dim3 gridY(mblocks, RGROUP);
    dim3 gridL(mblocks, 1);
    const int ebl = (N_EDGES + 255) / 256;                  // 3125
    const int gate_blocks = (N_NODES * 32 + 255) / 256;
    const int scat_blocks = 2048;
    const int relu_blocks = (N_NODES * D + 255) / 256;

    // ---- bucket edges by relation (deterministic each call) ----
    zero_cnt_kernel<<<1, 32>>>();
    hist_kernel<<<ebl, 256>>>(rel);
    prefix_kernel<<<1, 32>>>();
    reorder_kernel<<<ebl, 256>>>(src, dst, nrm, rel);

    // ---- layer 0 ----
    gate_kernel<<<gate_blocks, 256>>>(h, gw0);
    gemm_tf32_kernel<<<gridL, 128, GEMM_SMEM>>>(h, lw0, H1p, b0, N_NODES, 0);
    for (int s = 0; s < NSTAGES; s++) {
        gemm_tf32_kernel<<<gridY, 128, GEMM_SMEM>>>(h, W0 + (size_t)s * RGROUP * D * D,
                                                    Yp, nullptr, N_NODES,
                                                    (size_t)N_NODES * D);
        scatter_stage_kernel<<<scat_blocks, 256>>>(H1p, s * RGROUP);
    }
    relu_kernel<<<relu_blocks, 256>>>(H1p, N_NODES * D);

    // ---- layer 1 ----
    gate_kernel<<<gate_blocks, 256>>>(H1p, gw1);
    gemm_tf32_kernel<<<gridL, 128, GEMM_SMEM>>>(H1p, lw1, out, b1, N_NODES, 0);
    for (int s = 0; s < NSTAGES; s++) {
        gemm_tf32_kernel<<<gridY, 128, GEMM_SMEM>>>(H1p, W1 + (size_t)s * RGROUP * D * D,
                                                    Yp, nullptr, N_NODES,
                                                    (size_t)N_NODES * D);
        scatter_stage_kernel<<<scat_blocks, 256>>>(out, s * RGROUP);
    }
    (void)in_sizes; (void)n_in; (void)out_size;
}

// round 6
// speedup vs baseline: 1.4898x; 1.0463x over previous
#include <cuda_runtime.h>
#include <cstdint>
#include <math.h>

#define N_NODES 50000
#define N_EDGES 800000
#define N_RELS  16
#define D       128
#define RGROUP  2
#define NSTAGES (N_RELS / RGROUP)

// ---------------- device scratch (static, no allocation) ----------------
__device__ float g_Yr[(size_t)RGROUP * N_NODES * D];  // 51.2 MB reused Y slab (L2-resident)
__device__ float g_G[(size_t)N_RELS * N_NODES];       // gate logits
__device__ float g_H1[(size_t)N_NODES * D];           // layer-0 output
__device__ int   g_src_s[N_EDGES];                    // rel-sorted edge arrays
__device__ int   g_dst_s[N_EDGES];
__device__ float g_norm_s[N_EDGES];
__device__ int   g_cnt[N_RELS];
__device__ int   g_off[N_RELS + 1];
__device__ int   g_cur[N_RELS];
// fragment-ordered tf32 weights (mma.sync B-fragment layout)
__device__ float g_Bf0[(size_t)N_RELS * D * D];
__device__ float g_Bf1[(size_t)N_RELS * D * D];
__device__ float g_BfL0[(size_t)D * D];
__device__ float g_BfL1[(size_t)D * D];

// ---------------- helpers ----------------
__device__ __forceinline__ float to_tf32(float x) {
    unsigned u;
    asm("cvt.rna.tf32.f32 %0, %1;" : "=r"(u) : "f"(x));
    return __uint_as_float(u);
}

// ---------------- edge bucketing (per call, deterministic) ----------------
__global__ void __launch_bounds__(32)
zero_cnt_kernel() {
    if (threadIdx.x < N_RELS) g_cnt[threadIdx.x] = 0;
}

__global__ void __launch_bounds__(256)
hist_kernel(const int* __restrict__ rel) {
    __shared__ int scnt[N_RELS];
    if (threadIdx.x < N_RELS) scnt[threadIdx.x] = 0;
    __syncthreads();
    int e = blockIdx.x * 256 + threadIdx.x;
    if (e < N_EDGES) atomicAdd(&scnt[rel[e]], 1);
    __syncthreads();
    if (threadIdx.x < N_RELS && scnt[threadIdx.x] > 0)
        atomicAdd(&g_cnt[threadIdx.x], scnt[threadIdx.x]);
}

__global__ void __launch_bounds__(32)
prefix_kernel() {
    if (threadIdx.x == 0) {
        int acc = 0;
        #pragma unroll
        for (int r = 0; r < N_RELS; r++) {
            g_off[r] = acc; g_cur[r] = acc; acc += g_cnt[r];
        }
        g_off[N_RELS] = acc;
    }
}

__global__ void __launch_bounds__(256)
reorder_kernel(const int* __restrict__ src, const int* __restrict__ dst,
               const float* __restrict__ nrm, const int* __restrict__ rel) {
    __shared__ int scnt[N_RELS];
    __shared__ int sbase[N_RELS];
    if (threadIdx.x < N_RELS) scnt[threadIdx.x] = 0;
    __syncthreads();
    int e = blockIdx.x * 256 + threadIdx.x;
    int r = 0, rank = 0;
    bool ok = (e < N_EDGES);
    if (ok) { r = rel[e]; rank = atomicAdd(&scnt[r], 1); }
    __syncthreads();
    if (threadIdx.x < N_RELS && scnt[threadIdx.x] > 0)
        sbase[threadIdx.x] = atomicAdd(&g_cur[threadIdx.x], scnt[threadIdx.x]);
    __syncthreads();
    if (ok) {
        int pos = sbase[r] + rank;
        g_src_s[pos] = src[e];
        g_dst_s[pos] = dst[e];
        g_norm_s[pos] = nrm[e];
    }
}

// ---------------- weight -> mma B-fragment order (tf32-rounded) ----------------
// W row-major [k][n]; fragment element for (k,n):
//   ks=k>>3, t=k&3, kslot=(k>>2)&1; w=n>>5, jn=(n>>3)&3, g=n&7; lane=g*4+t
//   idx = ((ks*4+w)*32 + lane)*8 + kslot*4 + jn
__global__ void __launch_bounds__(256)
prep_w_kernel(const float* __restrict__ W, float* __restrict__ Bf) {
    int r = blockIdx.y;
    int i = blockIdx.x * 256 + threadIdx.x;
    if (i >= D * D) return;
    int k = i >> 7, n = i & 127;
    int ks = k >> 3, t = k & 3, kslot = (k >> 2) & 1;
    int w = n >> 5, jn = (n >> 3) & 3, g = n & 7;
    int idx = ((ks * 4 + w) * 32 + (g * 4 + t)) * 8 + kslot * 4 + jn;
    Bf[(size_t)r * D * D + idx] = to_tf32(W[(size_t)r * D * D + i]);
}

// ---------------- fragment-packed tf32 mma.sync GEMM ----------------
// C tile = A(64 rows x 128) @ W (128x128), W given pre-fragmented.
// 128 threads = 4 warps; warp w: rows 0..63 x cols [w*32, w*32+32).
// smem: A-frag 16ks x 4im x 132 floats (33792B), B-frag 16384 floats (65536B)
#define AFRAG_CHUNK 132
#define AFRAG_FLOATS (16 * 4 * AFRAG_CHUNK)     // 8448
#define GEMM_SMEM ((AFRAG_FLOATS + 16384) * 4)  // 99328

extern __shared__ float smem_dyn[];

__global__ void __launch_bounds__(128, 2)
gemm_frag_kernel(const float* __restrict__ A,     // M x D fp32
                 const float* __restrict__ BfAll, // (gridDim.y x) 16384 fragment floats
                 float* __restrict__ C,
                 const float* __restrict__ bias,  // D or nullptr
                 int M, size_t c_rel_stride)
{
    float* As = smem_dyn;
    float* Bs = smem_dyn + AFRAG_FLOATS;

    const int ry = blockIdx.y;
    const float* Bf = BfAll + (size_t)ry * D * D;
    float* Cr = C + (size_t)ry * c_rel_stride;
    const int row0 = blockIdx.x * 64;
    const int tid = threadIdx.x;

    // B frag: straight coalesced copy (4096 float4)
    for (int i = tid; i < 4096; i += 128)
        ((float4*)Bs)[i] = __ldg((const float4*)Bf + i);

    // A: load 8 cols (one ks) per item, store to fragment layout
    for (int i = tid; i < 64 * 16; i += 128) {
        int rr = i & 63;
        int ksl = i >> 6;
        int gr = row0 + rr;
        float4 v0 = make_float4(0.f, 0.f, 0.f, 0.f);
        float4 v1 = make_float4(0.f, 0.f, 0.f, 0.f);
        if (gr < M) {
            v0 = *(const float4*)(A + (size_t)gr * D + ksl * 8);
            v1 = *(const float4*)(A + (size_t)gr * D + ksl * 8 + 4);
        }
        int im = rr >> 4, h2 = (rr >> 3) & 1, g = rr & 7;
        float* base = As + (ksl * 4 + im) * AFRAG_CHUNK + g * 16 + h2;
        base[0]  = to_tf32(v0.x);  base[4]  = to_tf32(v0.y);
        base[8]  = to_tf32(v0.z);  base[12] = to_tf32(v0.w);
        base[2]  = to_tf32(v1.x);  base[6]  = to_tf32(v1.y);
        base[10] = to_tf32(v1.z);  base[14] = to_tf32(v1.w);
    }
    __syncthreads();

    const int w = tid >> 5;
    const int lane = tid & 31;
    const int g = lane >> 2;
    const int t = lane & 3;

    float acc[4][4][4];
    #pragma unroll
    for (int im = 0; im < 4; im++)
        #pragma unroll
        for (int jn = 0; jn < 4; jn++)
            #pragma unroll
            for (int k = 0; k < 4; k++) acc[im][jn][k] = 0.f;

    #pragma unroll
    for (int ks = 0; ks < 16; ks++) {
        float4 a4[4];
        #pragma unroll
        for (int im = 0; im < 4; im++)
            a4[im] = *(const float4*)(As + (ks * 4 + im) * AFRAG_CHUNK + lane * 4);
        const float* bp = Bs + ((ks * 4 + w) * 32 + lane) * 8;
        float4 b0 = *(const float4*)bp;
        float4 b1 = *(const float4*)(bp + 4);
        float b0a[4] = {b0.x, b0.y, b0.z, b0.w};
        float b1a[4] = {b1.x, b1.y, b1.z, b1.w};
        #pragma unroll
        for (int im = 0; im < 4; im++) {
            unsigned au0 = __float_as_uint(a4[im].x);
            unsigned au1 = __float_as_uint(a4[im].y);
            unsigned au2 = __float_as_uint(a4[im].z);
            unsigned au3 = __float_as_uint(a4[im].w);
            #pragma unroll
            for (int jn = 0; jn < 4; jn++) {
                asm volatile(
                    "mma.sync.aligned.m16n8k8.row.col.f32.tf32.tf32.f32 "
                    "{%0,%1,%2,%3}, {%4,%5,%6,%7}, {%8,%9}, {%0,%1,%2,%3};"
                    : "+f"(acc[im][jn][0]), "+f"(acc[im][jn][1]),
                      "+f"(acc[im][jn][2]), "+f"(acc[im][jn][3])
                    : "r"(au0), "r"(au1), "r"(au2), "r"(au3),
                      "r"(__float_as_uint(b0a[jn])), "r"(__float_as_uint(b1a[jn])));
            }
        }
    }

    #pragma unroll
    for (int im = 0; im < 4; im++) {
        int rb = row0 + im * 16 + g;
        #pragma unroll
        for (int jn = 0; jn < 4; jn++) {
            int col = w * 32 + jn * 8 + 2 * t;
            float bx = 0.f, by = 0.f;
            if (bias) { bx = __ldg(bias + col); by = __ldg(bias + col + 1); }
            if (rb < M) {
                float2 v = make_float2(acc[im][jn][0] + bx, acc[im][jn][1] + by);
                *(float2*)(Cr + (size_t)rb * D + col) = v;
            }
            if (rb + 8 < M) {
                float2 v = make_float2(acc[im][jn][2] + bx, acc[im][jn][3] + by);
                *(float2*)(Cr + (size_t)(rb + 8) * D + col) = v;
            }
        }
    }
}

// ---------------- gate logits: G[r,n] = h[n,:] . gate_w[r,:] ----------------
__global__ void __launch_bounds__(256)
gate_kernel(const float* __restrict__ H, const float* __restrict__ GW)
{
    int node = (blockIdx.x * blockDim.x + threadIdx.x) >> 5;
    int lane = threadIdx.x & 31;
    if (node >= N_NODES) return;
    float4 hv = *(const float4*)(H + (size_t)node * D + lane * 4);
    #pragma unroll
    for (int r = 0; r < N_RELS; r++) {
        float4 wv = *(const float4*)(GW + r * D + lane * 4);
        float p = hv.x * wv.x + hv.y * wv.y + hv.z * wv.z + hv.w * wv.w;
        #pragma unroll
        for (int off = 16; off > 0; off >>= 1)
            p += __shfl_xor_sync(0xFFFFFFFFu, p, off);
        if (lane == 0) g_G[(size_t)r * N_NODES + node] = p;
    }
}

// ---------------- stage scatter: edges of rels [r0, r0+RGROUP) ----------------
__global__ void __launch_bounds__(256)
scatter_stage_kernel(float* __restrict__ out, int r0)
{
    const int gw = (blockIdx.x * blockDim.x + threadIdx.x) >> 5;
    const int lane = threadIdx.x & 31;
    const int nwarp = (gridDim.x * blockDim.x) >> 5;
    const int e0 = g_off[r0];
    const int mid = g_off[r0 + 1];
    const int e1 = g_off[r0 + RGROUP];
    for (int p = e0 + gw; p < e1; p += nwarp) {
        int s = __ldg(g_src_s + p);
        int d = __ldg(g_dst_s + p);
        int r = (p < mid) ? r0 : (r0 + 1);
        float gl = g_G[(size_t)r * N_NODES + s];
        float coef = __ldg(g_norm_s + p) / (1.f + __expf(-gl));
        int local = r - r0;
        float4 v = *(const float4*)(&g_Yr[((size_t)local * N_NODES + s) * D + lane * 4]);
        float* ptr = out + (size_t)d * D + lane * 4;
        asm volatile("red.global.add.v4.f32 [%0], {%1,%2,%3,%4};"
                     :: "l"(ptr), "f"(v.x * coef), "f"(v.y * coef),
                        "f"(v.z * coef), "f"(v.w * coef)
                     : "memory");
    }
}

// ---------------- relu ----------------
__global__ void __launch_bounds__(256)
relu_kernel(float* __restrict__ x, int n)
{
    int i = blockIdx.x * blockDim.x + threadIdx.x;
    if (i < n) x[i] = fmaxf(x[i], 0.f);
}

// ---------------- launch ----------------
extern "C" void kernel_launch(void* const* d_in, const int* in_sizes, int n_in,
                              void* d_out, int out_size)
{
    const float* h   = (const float*)d_in[0];
    const float* nrm = (const float*)d_in[1];
    const float* W0  = (const float*)d_in[2];
    const float* b0  = (const float*)d_in[3];
    const float* lw0 = (const float*)d_in[4];
    const float* gw0 = (const float*)d_in[5];
    const float* W1  = (const float*)d_in[6];
    const float* b1  = (const float*)d_in[7];
    const float* lw1 = (const float*)d_in[8];
    const float* gw1 = (const float*)d_in[9];
    const int*   src = (const int*)d_in[10];
    const int*   dst = (const int*)d_in[11];
    const int*   rel = (const int*)d_in[12];
    float* out = (float*)d_out;

    cudaFuncSetAttribute(gemm_frag_kernel,
                         cudaFuncAttributeMaxDynamicSharedMemorySize, GEMM_SMEM);

    float *Yp, *H1p, *Bf0, *Bf1, *BfL0, *BfL1;
    cudaGetSymbolAddress((void**)&Yp, g_Yr);
    cudaGetSymbolAddress((void**)&H1p, g_H1);
    cudaGetSymbolAddress((void**)&Bf0, g_Bf0);
    cudaGetSymbolAddress((void**)&Bf1, g_Bf1);
    cudaGetSymbolAddress((void**)&BfL0, g_BfL0);
    cudaGetSymbolAddress((void**)&BfL1, g_BfL1);

    const int mblocks = (N_NODES + 63) / 64;                // 782
    dim3 gridY(mblocks, RGROUP);
    dim3 gridL(mblocks, 1);
    dim3 gridP((D * D + 255) / 256, N_RELS);
    dim3 gridPL((D * D + 255) / 256, 1);
    const int ebl = (N_EDGES + 255) / 256;
    const int gate_blocks = (N_NODES * 32 + 255) / 256;
    const int scat_blocks = 2048;
    const int relu_blocks = (N_NODES * D + 255) / 256;
    const size_t yst = (size_t)N_NODES * D;

    // launch index 3 = first rel-GEMM stage (gets profiled)
    zero_cnt_kernel<<<1, 32>>>();                                    // 0
    hist_kernel<<<ebl, 256>>>(rel);                                  // 1
    prep_w_kernel<<<gridP, 256>>>(W0, Bf0);                          // 2
    gemm_frag_kernel<<<gridY, 128, GEMM_SMEM>>>(h, Bf0, Yp, nullptr, // 3
                                                N_NODES, yst);
    prefix_kernel<<<1, 32>>>();                                      // 4
    reorder_kernel<<<ebl, 256>>>(src, dst, nrm, rel);                // 5
    prep_w_kernel<<<gridPL, 256>>>(lw0, BfL0);                       // 6
    prep_w_kernel<<<gridP, 256>>>(W1, Bf1);                          // 7
    prep_w_kernel<<<gridPL, 256>>>(lw1, BfL1);                       // 8
    gate_kernel<<<gate_blocks, 256>>>(h, gw0);                       // 9
    gemm_frag_kernel<<<gridL, 128, GEMM_SMEM>>>(h, BfL0, H1p, b0, N_NODES, 0);
    scatter_stage_kernel<<<scat_blocks, 256>>>(H1p, 0);
    for (int s = 1; s < NSTAGES; s++) {
        gemm_frag_kernel<<<gridY, 128, GEMM_SMEM>>>(h, Bf0 + (size_t)s * RGROUP * D * D,
                                                    Yp, nullptr, N_NODES, yst);
        scatter_stage_kernel<<<scat_blocks, 256>>>(H1p, s * RGROUP);
    }
    relu_kernel<<<relu_blocks, 256>>>(H1p, N_NODES * D);

    // ---- layer 1 ----
    gate_kernel<<<gate_blocks, 256>>>(H1p, gw1);
    gemm_frag_kernel<<<gridL, 128, GEMM_SMEM>>>(H1p, BfL1, out, b1, N_NODES, 0);
    for (int s = 0; s < NSTAGES; s++) {
        gemm_frag_kernel<<<gridY, 128, GEMM_SMEM>>>(H1p, Bf1 + (size_t)s * RGROUP * D * D,
                                                    Yp, nullptr, N_NODES, yst);
        scatter_stage_kernel<<<scat_blocks, 256>>>(out, s * RGROUP);
    }
    (void)in_sizes; (void)n_in; (void)out_size;
}

// round 8
// speedup vs baseline: 1.7760x; 1.1921x over previous
#include <cuda_runtime.h>
#include <cstdint>
#include <math.h>

#define N_NODES 50000
#define N_EDGES 800000
#define N_RELS  16
#define D       128
#define RGROUP  2
#define NSTAGES (N_RELS / RGROUP)

// ---------------- device scratch (static, no allocation) ----------------
__device__ float g_Yr[(size_t)RGROUP * N_NODES * D];  // 51.2 MB reused Y slab (L2-resident)
__device__ float g_G[(size_t)N_RELS * N_NODES];       // gate logits
__device__ float g_H1[(size_t)N_NODES * D];           // layer-0 output
__device__ int   g_src_s[N_EDGES];                    // rel-sorted edge arrays
__device__ int   g_dst_s[N_EDGES];
__device__ float g_norm_s[N_EDGES];
__device__ int   g_cnt[N_RELS];
__device__ int   g_off[N_RELS + 1];
__device__ int   g_cur[N_RELS];
// fragment-ordered tf32 weights (mma.sync B-fragment layout)
__device__ float g_Bf0[(size_t)N_RELS * D * D];
__device__ float g_Bf1[(size_t)N_RELS * D * D];
__device__ float g_BfL0[(size_t)D * D];
__device__ float g_BfL1[(size_t)D * D];

// ---------------- helpers ----------------
__device__ __forceinline__ float to_tf32(float x) {
    unsigned u;
    asm("cvt.rna.tf32.f32 %0, %1;" : "=r"(u) : "f"(x));
    return __uint_as_float(u);
}

// ---------------- edge bucketing (per call, deterministic) ----------------
__global__ void __launch_bounds__(32)
zero_cnt_kernel() {
    if (threadIdx.x < N_RELS) g_cnt[threadIdx.x] = 0;
}

__global__ void __launch_bounds__(256)
hist_kernel(const int* __restrict__ rel) {
    __shared__ int scnt[N_RELS];
    if (threadIdx.x < N_RELS) scnt[threadIdx.x] = 0;
    __syncthreads();
    int e = blockIdx.x * 256 + threadIdx.x;
    if (e < N_EDGES) atomicAdd(&scnt[rel[e]], 1);
    __syncthreads();
    if (threadIdx.x < N_RELS && scnt[threadIdx.x] > 0)
        atomicAdd(&g_cnt[threadIdx.x], scnt[threadIdx.x]);
}

__global__ void __launch_bounds__(32)
prefix_kernel() {
    if (threadIdx.x == 0) {
        int acc = 0;
        #pragma unroll
        for (int r = 0; r < N_RELS; r++) {
            g_off[r] = acc; g_cur[r] = acc; acc += g_cnt[r];
        }
        g_off[N_RELS] = acc;
    }
}

__global__ void __launch_bounds__(256)
reorder_kernel(const int* __restrict__ src, const int* __restrict__ dst,
               const float* __restrict__ nrm, const int* __restrict__ rel) {
    __shared__ int scnt[N_RELS];
    __shared__ int sbase[N_RELS];
    if (threadIdx.x < N_RELS) scnt[threadIdx.x] = 0;
    __syncthreads();
    int e = blockIdx.x * 256 + threadIdx.x;
    int r = 0, rank = 0;
    bool ok = (e < N_EDGES);
    if (ok) { r = rel[e]; rank = atomicAdd(&scnt[r], 1); }
    __syncthreads();
    if (threadIdx.x < N_RELS && scnt[threadIdx.x] > 0)
        sbase[threadIdx.x] = atomicAdd(&g_cur[threadIdx.x], scnt[threadIdx.x]);
    __syncthreads();
    if (ok) {
        int pos = sbase[r] + rank;
        g_src_s[pos] = src[e];
        g_dst_s[pos] = dst[e];
        g_norm_s[pos] = nrm[e];
    }
}

// ---------------- weight -> mma B-fragment order (tf32-rounded) ----------------
// W row-major [k][n]; fragment element for (k,n):
//   ks=k>>3, t=k&3, kslot=(k>>2)&1; w=n>>5, jn=(n>>3)&3, g=n&7; lane=g*4+t
//   idx = ((ks*4+w)*32 + lane)*8 + kslot*4 + jn
__global__ void __launch_bounds__(256)
prep_w_kernel(const float* __restrict__ W, float* __restrict__ Bf) {
    int r = blockIdx.y;
    int i = blockIdx.x * 256 + threadIdx.x;
    if (i >= D * D) return;
    int k = i >> 7, n = i & 127;
    int ks = k >> 3, t = k & 3, kslot = (k >> 2) & 1;
    int w = n >> 5, jn = (n >> 3) & 3, g = n & 7;
    int idx = ((ks * 4 + w) * 32 + (g * 4 + t)) * 8 + kslot * 4 + jn;
    Bf[(size_t)r * D * D + idx] = to_tf32(W[(size_t)r * D * D + i]);
}

// ---------------- fragment-packed tf32 mma.sync GEMM ----------------
// C tile = A(64 rows x 128) @ W (128x128). A-frag in smem (33KB);
// B fragments streamed from GMEM (L2-hot) into regs, double-buffered.
// 128 threads = 4 warps; warp w: rows 0..63 x cols [w*32, w*32+32).
#define AFRAG_CHUNK 132
#define AFRAG_FLOATS (16 * 4 * AFRAG_CHUNK)     // 8448
#define GEMM_SMEM (AFRAG_FLOATS * 4)            // 33792

extern __shared__ float smem_dyn[];

#define MMA4(IM, B0, B1)                                                        \
    asm volatile(                                                               \
        "mma.sync.aligned.m16n8k8.row.col.f32.tf32.tf32.f32 "                   \
        "{%0,%1,%2,%3}, {%4,%5,%6,%7}, {%8,%9}, {%0,%1,%2,%3};"                 \
        : "+f"(acc[IM][0]), "+f"(acc[IM][1]), "+f"(acc[IM][2]), "+f"(acc[IM][3])\
        : "r"(au0), "r"(au1), "r"(au2), "r"(au3),                               \
          "r"(__float_as_uint(B0)), "r"(__float_as_uint(B1)))

__global__ void __launch_bounds__(128, 4)
gemm_frag_kernel(const float* __restrict__ A,     // M x D fp32
                 const float* __restrict__ BfAll, // (gridDim.y x) 16384 fragment floats
                 float* __restrict__ C,
                 const float* __restrict__ bias,  // D or nullptr
                 int M, size_t c_rel_stride)
{
    float* As = smem_dyn;

    const int ry = blockIdx.y;
    const float* Bf = BfAll + (size_t)ry * D * D;
    float* Cr = C + (size_t)ry * c_rel_stride;
    const int row0 = blockIdx.x * 64;
    const int tid = threadIdx.x;
    const int w = tid >> 5;
    const int lane = tid & 31;
    const int g = lane >> 2;
    const int t = lane & 3;

    // A: load 8 cols (one ks) per item, store to fragment layout
    for (int i = tid; i < 64 * 16; i += 128) {
        int rr = i & 63;
        int ksl = i >> 6;
        int gr = row0 + rr;
        float4 v0 = make_float4(0.f, 0.f, 0.f, 0.f);
        float4 v1 = make_float4(0.f, 0.f, 0.f, 0.f);
        if (gr < M) {
            v0 = *(const float4*)(A + (size_t)gr * D + ksl * 8);
            v1 = *(const float4*)(A + (size_t)gr * D + ksl * 8 + 4);
        }
        int im = rr >> 4, h2 = (rr >> 3) & 1, gg = rr & 7;
        float* base = As + (ksl * 4 + im) * AFRAG_CHUNK + gg * 16 + h2;
        base[0]  = to_tf32(v0.x);  base[4]  = to_tf32(v0.y);
        base[8]  = to_tf32(v0.z);  base[12] = to_tf32(v0.w);
        base[2]  = to_tf32(v1.x);  base[6]  = to_tf32(v1.y);
        base[10] = to_tf32(v1.z);  base[14] = to_tf32(v1.w);
    }
    __syncthreads();

    float acc4[4][4][4];
    #pragma unroll
    for (int im = 0; im < 4; im++)
        #pragma unroll
        for (int jn = 0; jn < 4; jn++)
            #pragma unroll
            for (int k = 0; k < 4; k++) acc4[im][jn][k] = 0.f;

    // B fragment base for this thread; per-ks stride = 256 float4
    const float4* bg = (const float4*)Bf + ((size_t)w * 32 + lane) * 2;
    float4 b0c = __ldg(bg);
    float4 b1c = __ldg(bg + 1);

    #pragma unroll
    for (int ks = 0; ks < 16; ks++) {
        // prefetch next ks B (clamped duplicate at the tail)
        int nks = (ks < 15) ? (ks + 1) : 15;
        float4 b0n = __ldg(bg + nks * 256);
        float4 b1n = __ldg(bg + nks * 256 + 1);

        float4 a4[4];
        #pragma unroll
        for (int im = 0; im < 4; im++)
            a4[im] = *(const float4*)(As + (ks * 4 + im) * AFRAG_CHUNK + lane * 4);

        #pragma unroll
        for (int jn = 0; jn < 4; jn++) {
            float b0v = (jn == 0) ? b0c.x : (jn == 1) ? b0c.y : (jn == 2) ? b0c.z : b0c.w;
            float b1v = (jn == 0) ? b1c.x : (jn == 1) ? b1c.y : (jn == 2) ? b1c.z : b1c.w;
            #pragma unroll
            for (int im = 0; im < 4; im++) {
                unsigned au0 = __float_as_uint(a4[im].x);
                unsigned au1 = __float_as_uint(a4[im].y);
                unsigned au2 = __float_as_uint(a4[im].z);
                unsigned au3 = __float_as_uint(a4[im].w);
                float (*acc)[4] = &acc4[0][jn];
                // expand: acc4[im][jn]
                asm volatile(
                    "mma.sync.aligned.m16n8k8.row.col.f32.tf32.tf32.f32 "
                    "{%0,%1,%2,%3}, {%4,%5,%6,%7}, {%8,%9}, {%0,%1,%2,%3};"
                    : "+f"(acc4[im][jn][0]), "+f"(acc4[im][jn][1]),
                      "+f"(acc4[im][jn][2]), "+f"(acc4[im][jn][3])
                    : "r"(au0), "r"(au1), "r"(au2), "r"(au3),
                      "r"(__float_as_uint(b0v)), "r"(__float_as_uint(b1v)));
                (void)acc;
            }
        }
        b0c = b0n; b1c = b1n;
    }

    #pragma unroll
    for (int im = 0; im < 4; im++) {
        int rb = row0 + im * 16 + g;
        #pragma unroll
        for (int jn = 0; jn < 4; jn++) {
            int col = w * 32 + jn * 8 + 2 * t;
            float bx = 0.f, by = 0.f;
            if (bias) { bx = __ldg(bias + col); by = __ldg(bias + col + 1); }
            if (rb < M) {
                float2 v = make_float2(acc4[im][jn][0] + bx, acc4[im][jn][1] + by);
                *(float2*)(Cr + (size_t)rb * D + col) = v;
            }
            if (rb + 8 < M) {
                float2 v = make_float2(acc4[im][jn][2] + bx, acc4[im][jn][3] + by);
                *(float2*)(Cr + (size_t)(rb + 8) * D + col) = v;
            }
        }
    }
}

// ---------------- gate logits: G[r,n] = h[n,:] . gate_w[r,:] ----------------
__global__ void __launch_bounds__(256)
gate_kernel(const float* __restrict__ H, const float* __restrict__ GW)
{
    int node = (blockIdx.x * blockDim.x + threadIdx.x) >> 5;
    int lane = threadIdx.x & 31;
    if (node >= N_NODES) return;
    float4 hv = *(const float4*)(H + (size_t)node * D + lane * 4);
    #pragma unroll
    for (int r = 0; r < N_RELS; r++) {
        float4 wv = *(const float4*)(GW + r * D + lane * 4);
        float p = hv.x * wv.x + hv.y * wv.y + hv.z * wv.z + hv.w * wv.w;
        #pragma unroll
        for (int off = 16; off > 0; off >>= 1)
            p += __shfl_xor_sync(0xFFFFFFFFu, p, off);
        if (lane == 0) g_G[(size_t)r * N_NODES + node] = p;
    }
}

// ---------------- stage scatter: edges of rels [r0, r0+RGROUP) ----------------
__global__ void __launch_bounds__(256)
scatter_stage_kernel(float* __restrict__ out, int r0)
{
    const int gw = (blockIdx.x * blockDim.x + threadIdx.x) >> 5;
    const int lane = threadIdx.x & 31;
    const int nwarp = (gridDim.x * blockDim.x) >> 5;
    const int e0 = g_off[r0];
    const int mid = g_off[r0 + 1];
    const int e1 = g_off[r0 + RGROUP];
    for (int p = e0 + gw; p < e1; p += nwarp) {
        int s = __ldg(g_src_s + p);
        int d = __ldg(g_dst_s + p);
        int r = (p < mid) ? r0 : (r0 + 1);
        float gl = g_G[(size_t)r * N_NODES + s];
        float coef = __ldg(g_norm_s + p) / (1.f + __expf(-gl));
        int local = r - r0;
        float4 v = *(const float4*)(&g_Yr[((size_t)local * N_NODES + s) * D + lane * 4]);
        float* ptr = out + (size_t)d * D + lane * 4;
        asm volatile("red.global.add.v4.f32 [%0], {%1,%2,%3,%4};"
                     :: "l"(ptr), "f"(v.x * coef), "f"(v.y * coef),
                        "f"(v.z * coef), "f"(v.w * coef)
                     : "memory");
    }
}

// ---------------- relu ----------------
__global__ void __launch_bounds__(256)
relu_kernel(float* __restrict__ x, int n)
{
    int i = blockIdx.x * blockDim.x + threadIdx.x;
    if (i < n) x[i] = fmaxf(x[i], 0.f);
}

// ---------------- launch ----------------
extern "C" void kernel_launch(void* const* d_in, const int* in_sizes, int n_in,
                              void* d_out, int out_size)
{
    const float* h   = (const float*)d_in[0];
    const float* nrm = (const float*)d_in[1];
    const float* W0  = (const float*)d_in[2];
    const float* b0  = (const float*)d_in[3];
    const float* lw0 = (const float*)d_in[4];
    const float* gw0 = (const float*)d_in[5];
    const float* W1  = (const float*)d_in[6];
    const float* b1  = (const float*)d_in[7];
    const float* lw1 = (const float*)d_in[8];
    const float* gw1 = (const float*)d_in[9];
    const int*   src = (const int*)d_in[10];
    const int*   dst = (const int*)d_in[11];
    const int*   rel = (const int*)d_in[12];
    float* out = (float*)d_out;

    cudaFuncSetAttribute(gemm_frag_kernel,
                         cudaFuncAttributeMaxDynamicSharedMemorySize, GEMM_SMEM);

    float *Yp, *H1p, *Bf0, *Bf1, *BfL0, *BfL1;
    cudaGetSymbolAddress((void**)&Yp, g_Yr);
    cudaGetSymbolAddress((void**)&H1p, g_H1);
    cudaGetSymbolAddress((void**)&Bf0, g_Bf0);
    cudaGetSymbolAddress((void**)&Bf1, g_Bf1);
    cudaGetSymbolAddress((void**)&BfL0, g_BfL0);
    cudaGetSymbolAddress((void**)&BfL1, g_BfL1);

    const int mblocks = (N_NODES + 63) / 64;                // 782
    dim3 gridY(mblocks, RGROUP);
    dim3 gridL(mblocks, 1);
    dim3 gridP((D * D + 255) / 256, N_RELS);
    dim3 gridPL((D * D + 255) / 256, 1);
    const int ebl = (N_EDGES + 255) / 256;
    const int gate_blocks = (N_NODES * 32 + 255) / 256;
    const int scat_blocks = 2048;
    const int relu_blocks = (N_NODES * D + 255) / 256;
    const size_t yst = (size_t)N_NODES * D;

    // launch index 3 = first rel-GEMM stage (gets profiled)
    zero_cnt_kernel<<<1, 32>>>();                                    // 0
    hist_kernel<<<ebl, 256>>>(rel);                                  // 1
    prep_w_kernel<<<gridP, 256>>>(W0, Bf0);                          // 2
    gemm_frag_kernel<<<gridY, 128, GEMM_SMEM>>>(h, Bf0, Yp, nullptr, // 3
                                                N_NODES, yst);
    prefix_kernel<<<1, 32>>>();                                      // 4
    reorder_kernel<<<ebl, 256>>>(src, dst, nrm, rel);                // 5
    prep_w_kernel<<<gridPL, 256>>>(lw0, BfL0);                       // 6
    prep_w_kernel<<<gridP, 256>>>(W1, Bf1);                          // 7
    prep_w_kernel<<<gridPL, 256>>>(lw1, BfL1);                       // 8
    gate_kernel<<<gate_blocks, 256>>>(h, gw0);                       // 9
    gemm_frag_kernel<<<gridL, 128, GEMM_SMEM>>>(h, BfL0, H1p, b0, N_NODES, 0);
    scatter_stage_kernel<<<scat_blocks, 256>>>(H1p, 0);
    for (int s = 1; s < NSTAGES; s++) {
        gemm_frag_kernel<<<gridY, 128, GEMM_SMEM>>>(h, Bf0 + (size_t)s * RGROUP * D * D,
                                                    Yp, nullptr, N_NODES, yst);
        scatter_stage_kernel<<<scat_blocks, 256>>>(H1p, s * RGROUP);
    }
    relu_kernel<<<relu_blocks, 256>>>(H1p, N_NODES * D);

    // ---- layer 1 ----
    gate_kernel<<<gate_blocks, 256>>>(H1p, gw1);
    gemm_frag_kernel<<<gridL, 128, GEMM_SMEM>>>(H1p, BfL1, out, b1, N_NODES, 0);
    for (int s = 0; s < NSTAGES; s++) {
        gemm_frag_kernel<<<gridY, 128, GEMM_SMEM>>>(H1p, Bf1 + (size_t)s * RGROUP * D * D,
                                                    Yp, nullptr, N_NODES, yst);
        scatter_stage_kernel<<<scat_blocks, 256>>>(out, s * RGROUP);
    }
    (void)in_sizes; (void)n_in; (void)out_size;
}